// round 2
// baseline (speedup 1.0000x reference)
#include <cuda_runtime.h>

#define N_NODES 20000
#define N_EDGES 240000
#define IN_DIM  20
#define SH_DIM  16
#define OUT_DIM 360   // 20 (mlp) + 20 (sender sum) + 320 (tensor product)

// ---- scratch (zero-initialized at module load; g_count invariant: ==0 on
//      entry to kernel_launch, restored by k_scan each call) ----
__device__ __align__(16) int g_count[N_NODES];
__device__ __align__(16) int g_start[N_NODES + 1];
__device__ __align__(16) int g_cursor[N_NODES];
__device__ __align__(16) int g_edge_row[N_EDGES];

// ============================================================================
// K1: fused per-node MLP (cols 0..19) + destination-degree histogram.
//     Requires g_count == 0 on entry (module init / restored by k_scan).
// ============================================================================
__global__ void k_mlp_hist(const float* __restrict__ x,
                           const float* __restrict__ Wpre,  const float* __restrict__ bpre,
                           const float* __restrict__ Wpost, const float* __restrict__ bpost,
                           const float* __restrict__ Wsc,   const float* __restrict__ bsc,
                           const int*   __restrict__ ei,
                           float* __restrict__ out)
{
    __shared__ float sWpre[400], sWpost[400], sWsc[400], sb[60];
    for (int i = threadIdx.x; i < 400; i += blockDim.x) {
        sWpre[i]  = Wpre[i];
        sWpost[i] = Wpost[i];
        sWsc[i]   = Wsc[i];
    }
    if (threadIdx.x < 20) {
        sb[threadIdx.x]      = bpre[threadIdx.x];
        sb[20 + threadIdx.x] = bpost[threadIdx.x];
        sb[40 + threadIdx.x] = bsc[threadIdx.x];
    }

    const int tid    = blockIdx.x * blockDim.x + threadIdx.x;
    const int stride = gridDim.x * blockDim.x;

    // ---- histogram over destination (col) indices, 4 edges / iteration ----
    const int4* cols4 = (const int4*)(ei + N_EDGES);
    for (int i = tid; i < N_EDGES / 4; i += stride) {
        int4 c = __ldg(&cols4[i]);
        atomicAdd(&g_count[c.x], 1);
        atomicAdd(&g_count[c.y], 1);
        atomicAdd(&g_count[c.z], 1);
        atomicAdd(&g_count[c.w], 1);
    }

    __syncthreads();

    // ---- per-node MLP ----
    const int n = tid;
    if (n >= N_NODES) return;

    float xr[IN_DIM];
#pragma unroll
    for (int k = 0; k < IN_DIM; k++) xr[k] = x[n * IN_DIM + k];

    float pre[IN_DIM];
#pragma unroll
    for (int i = 0; i < IN_DIM; i++) {
        float a = sb[i];
#pragma unroll
        for (int k = 0; k < IN_DIM; k++) a = fmaf(xr[k], sWpre[i * IN_DIM + k], a);
        pre[i] = fmaxf(a, 0.0f);
    }

#pragma unroll
    for (int i = 0; i < IN_DIM; i++) {
        float a = sb[20 + i] + sb[40 + i];
#pragma unroll
        for (int k = 0; k < IN_DIM; k++) {
            a = fmaf(pre[k], sWpost[i * IN_DIM + k], a);
            a = fmaf(xr[k],  sWsc[i * IN_DIM + k],  a);
        }
        out[n * OUT_DIM + i] = a;
    }
}

// ============================================================================
// K2: exclusive scan of counts -> g_start, g_cursor; re-zeros g_count.
//     Single block, 1024 threads, 20 elements/thread, shfl warp scan.
// ============================================================================
__global__ void k_scan()
{
    __shared__ int warp_sum[32];
    __shared__ int s_total;
    const int t    = threadIdx.x;
    const int lane = t & 31;
    const int wid  = t >> 5;
    const int base = t * 20;
    const bool active = (base < N_NODES);   // t < 1000

    int c[20];
    int s = 0;
    if (active) {
        const int4* p4 = (const int4*)(g_count + base);
#pragma unroll
        for (int v = 0; v < 5; v++) {
            int4 q = p4[v];
            c[v * 4 + 0] = q.x; c[v * 4 + 1] = q.y;
            c[v * 4 + 2] = q.z; c[v * 4 + 3] = q.w;
        }
#pragma unroll
        for (int k = 0; k < 20; k++) s += c[k];
    } else {
#pragma unroll
        for (int k = 0; k < 20; k++) c[k] = 0;
    }

    // inclusive warp scan of per-thread sums
    int inc = s;
#pragma unroll
    for (int off = 1; off < 32; off <<= 1) {
        int v = __shfl_up_sync(0xffffffffu, inc, off);
        if (lane >= off) inc += v;
    }
    if (lane == 31) warp_sum[wid] = inc;
    __syncthreads();

    if (wid == 0) {
        int ws = warp_sum[lane];
        int wi = ws;
#pragma unroll
        for (int off = 1; off < 32; off <<= 1) {
            int v = __shfl_up_sync(0xffffffffu, wi, off);
            if (lane >= off) wi += v;
        }
        warp_sum[lane] = wi - ws;                 // exclusive warp prefix
        if (lane == 31) s_total = wi;
    }
    __syncthreads();

    if (active) {
        int run = warp_sum[wid] + (inc - s);      // exclusive prefix for this thread
#pragma unroll
        for (int k = 0; k < 20; k++) {
            g_start[base + k]  = run;
            g_cursor[base + k] = run;
            run += c[k];
        }
        // restore invariant for next replay
        int4* z4 = (int4*)(g_count + base);
#pragma unroll
        for (int v = 0; v < 5; v++) z4[v] = make_int4(0, 0, 0, 0);
    }
    if (t == 0) g_start[N_NODES] = s_total;
}

// ============================================================================
// K3: scatter edge row-ids into destination-sorted order (4 edges/thread)
// ============================================================================
__global__ void k_scatter(const int* __restrict__ ei)
{
    int i = blockIdx.x * blockDim.x + threadIdx.x;
    if (i >= N_EDGES / 4) return;
    int4 r = __ldg(&((const int4*)ei)[i]);
    int4 c = __ldg(&((const int4*)(ei + N_EDGES))[i]);
    int s0 = atomicAdd(&g_cursor[c.x], 1);
    int s1 = atomicAdd(&g_cursor[c.y], 1);
    int s2 = atomicAdd(&g_cursor[c.z], 1);
    int s3 = atomicAdd(&g_cursor[c.w], 1);
    g_edge_row[s0] = r.x;
    g_edge_row[s1] = r.y;
    g_edge_row[s2] = r.z;
    g_edge_row[s3] = r.w;
}

// ============================================================================
// K4: gather-aggregate — one warp per destination node, depth-1 software
//     pipeline on the edge_row -> pos dependent chain.
// ============================================================================
__global__ void k_aggr(const float* __restrict__ x,
                       const float* __restrict__ pos,
                       float* __restrict__ out)
{
    const int warp = (blockIdx.x * blockDim.x + threadIdx.x) >> 5;
    const int lane = threadIdx.x & 31;
    if (warp >= N_NODES) return;
    const int n = warp;

    const int s0 = g_start[n];
    const int s1 = g_start[n + 1];

    const float pnx = pos[n * 3 + 0];
    const float pny = pos[n * 3 + 1];
    const float pnz = pos[n * 3 + 2];

    float accS = 0.0f;
    float acc[SH_DIM];
#pragma unroll
    for (int j = 0; j < SH_DIM; j++) acc[j] = 0.0f;

    int   r_next = 0;
    float qx = 0.f, qy = 0.f, qz = 0.f;
    if (s0 < s1) {
        r_next = g_edge_row[s0];
        qx = pos[r_next * 3 + 0];
        qy = pos[r_next * 3 + 1];
        qz = pos[r_next * 3 + 2];
    }

    for (int slot = s0; slot < s1; slot++) {
        const int   r  = r_next;
        const float px = qx, py = qy, pz = qz;

        // prefetch next edge while we do this edge's math
        if (slot + 1 < s1) {
            r_next = g_edge_row[slot + 1];
            qx = pos[r_next * 3 + 0];
            qy = pos[r_next * 3 + 1];
            qz = pos[r_next * 3 + 2];
        }

        // issue the sender gather early too
        const float s = (lane < IN_DIM) ? x[r * IN_DIM + lane] : 0.0f;

        float rx = pnx - px, ry = pny - py, rz = pnz - pz;
        float inv = rsqrtf(fmaf(rx, rx, fmaf(ry, ry, fmaf(rz, rz, 1e-12f))));
        float X = rx * inv, Y = ry * inv, Z = rz * inv;
        float X2 = X * X, Y2 = Y * Y, Z2 = Z * Z;

        float sh1  = 0.4886025119029199f * Y;
        float sh2  = 0.4886025119029199f * Z;
        float sh3  = 0.4886025119029199f * X;
        float sh4  = 1.0925484305920792f * X * Y;
        float sh5  = 1.0925484305920792f * Y * Z;
        float sh6  = 0.31539156525252005f * (3.0f * Z2 - 1.0f);
        float sh7  = 1.0925484305920792f * X * Z;
        float sh8  = 0.5462742152960396f * (X2 - Y2);
        float sh9  = 0.5900435899266435f * Y * (3.0f * X2 - Y2);
        float sh10 = 2.890611442640554f  * X * Y * Z;
        float sh11 = 0.4570457994644658f * Y * (5.0f * Z2 - 1.0f);
        float sh12 = 0.3731763325901154f * Z * (5.0f * Z2 - 3.0f);
        float sh13 = 0.4570457994644658f * X * (5.0f * Z2 - 1.0f);
        float sh14 = 1.445305721320277f  * Z * (X2 - Y2);
        float sh15 = 0.5900435899266435f * X * (X2 - 3.0f * Y2);

        accS += s;
        acc[0]  = fmaf(s, 0.28209479177387814f, acc[0]);
        acc[1]  = fmaf(s, sh1,  acc[1]);
        acc[2]  = fmaf(s, sh2,  acc[2]);
        acc[3]  = fmaf(s, sh3,  acc[3]);
        acc[4]  = fmaf(s, sh4,  acc[4]);
        acc[5]  = fmaf(s, sh5,  acc[5]);
        acc[6]  = fmaf(s, sh6,  acc[6]);
        acc[7]  = fmaf(s, sh7,  acc[7]);
        acc[8]  = fmaf(s, sh8,  acc[8]);
        acc[9]  = fmaf(s, sh9,  acc[9]);
        acc[10] = fmaf(s, sh10, acc[10]);
        acc[11] = fmaf(s, sh11, acc[11]);
        acc[12] = fmaf(s, sh12, acc[12]);
        acc[13] = fmaf(s, sh13, acc[13]);
        acc[14] = fmaf(s, sh14, acc[14]);
        acc[15] = fmaf(s, sh15, acc[15]);
    }

    if (lane < IN_DIM) {
        float* base = out + n * OUT_DIM;
        base[20 + lane] = accS;
        float4* p = (float4*)(base + 40 + lane * SH_DIM);
        p[0] = make_float4(acc[0],  acc[1],  acc[2],  acc[3]);
        p[1] = make_float4(acc[4],  acc[5],  acc[6],  acc[7]);
        p[2] = make_float4(acc[8],  acc[9],  acc[10], acc[11]);
        p[3] = make_float4(acc[12], acc[13], acc[14], acc[15]);
    }
}

// ============================================================================
extern "C" void kernel_launch(void* const* d_in, const int* in_sizes, int n_in,
                              void* d_out, int out_size)
{
    const float* x     = (const float*)d_in[0];
    const float* pos   = (const float*)d_in[1];
    const int*   ei    = (const int*)  d_in[2];
    const float* Wpre  = (const float*)d_in[3];
    const float* bpre  = (const float*)d_in[4];
    const float* Wpost = (const float*)d_in[5];
    const float* bpost = (const float*)d_in[6];
    const float* Wsc   = (const float*)d_in[7];
    const float* bsc   = (const float*)d_in[8];
    float* out = (float*)d_out;

    k_mlp_hist<<<(N_NODES + 255) / 256, 256>>>(x, Wpre, bpre, Wpost, bpost,
                                               Wsc, bsc, ei, out);
    k_scan<<<1, 1024>>>();
    k_scatter<<<(N_EDGES / 4 + 255) / 256, 256>>>(ei);
    k_aggr<<<(N_NODES * 32 + 255) / 256, 256>>>(x, pos, out);
}

// round 4
// speedup vs baseline: 1.3635x; 1.3635x over previous
#include <cuda_runtime.h>

#define N_NODES 20000
#define N_EDGES 240000
#define IN_DIM  20
#define SH_DIM  16
#define OUT_DIM 360   // 20 (mlp) + 20 (sender sum) + 320 (tensor product)

// ---- scratch (zero-initialized at module load; g_count invariant: ==0 on
//      entry to kernel_launch, restored by k_scan each call) ----
__device__ __align__(16) int   g_count[N_NODES];
__device__ __align__(16) int   g_start[N_NODES + 1];
__device__ __align__(16) int   g_cursor[N_NODES];
__device__ __align__(16) int   g_edge_row[N_EDGES];
__device__ __align__(16) float g_sh[N_EDGES * SH_DIM];   // dest-sorted SH per edge

// ============================================================================
// K1: per-node MLP (output cols 0..19)
// ============================================================================
__global__ void k_mlp(const float* __restrict__ x,
                      const float* __restrict__ Wpre,  const float* __restrict__ bpre,
                      const float* __restrict__ Wpost, const float* __restrict__ bpost,
                      const float* __restrict__ Wsc,   const float* __restrict__ bsc,
                      float* __restrict__ out)
{
    __shared__ float sWpre[400], sWpost[400], sWsc[400], sb[60];
    for (int i = threadIdx.x; i < 400; i += blockDim.x) {
        sWpre[i]  = Wpre[i];
        sWpost[i] = Wpost[i];
        sWsc[i]   = Wsc[i];
    }
    if (threadIdx.x < 20) {
        sb[threadIdx.x]      = bpre[threadIdx.x];
        sb[20 + threadIdx.x] = bpost[threadIdx.x];
        sb[40 + threadIdx.x] = bsc[threadIdx.x];
    }
    __syncthreads();

    const int n = blockIdx.x * blockDim.x + threadIdx.x;
    if (n >= N_NODES) return;

    float xr[IN_DIM];
#pragma unroll
    for (int k = 0; k < IN_DIM; k++) xr[k] = x[n * IN_DIM + k];

    float pre[IN_DIM];
#pragma unroll
    for (int i = 0; i < IN_DIM; i++) {
        float a = sb[i];
#pragma unroll
        for (int k = 0; k < IN_DIM; k++) a = fmaf(xr[k], sWpre[i * IN_DIM + k], a);
        pre[i] = fmaxf(a, 0.0f);
    }

#pragma unroll
    for (int i = 0; i < IN_DIM; i++) {
        float a = sb[20 + i] + sb[40 + i];
#pragma unroll
        for (int k = 0; k < IN_DIM; k++) {
            a = fmaf(pre[k], sWpost[i * IN_DIM + k], a);
            a = fmaf(xr[k],  sWsc[i * IN_DIM + k],  a);
        }
        out[n * OUT_DIM + i] = a;
    }
}

// ============================================================================
// K2: destination-degree histogram (1 edge / thread, coalesced)
// ============================================================================
__global__ void k_hist(const int* __restrict__ ei)
{
    int e = blockIdx.x * blockDim.x + threadIdx.x;
    if (e < N_EDGES) atomicAdd(&g_count[ei[N_EDGES + e]], 1);
}

// ============================================================================
// K3: exclusive scan of counts -> g_start, g_cursor; re-zeros g_count.
// ============================================================================
__global__ void k_scan()
{
    __shared__ int warp_sum[32];
    __shared__ int s_total;
    const int t    = threadIdx.x;
    const int lane = t & 31;
    const int wid  = t >> 5;
    const int base = t * 20;
    const bool active = (base < N_NODES);   // t < 1000

    int c[20];
    int s = 0;
    if (active) {
        const int4* p4 = (const int4*)(g_count + base);
#pragma unroll
        for (int v = 0; v < 5; v++) {
            int4 q = p4[v];
            c[v * 4 + 0] = q.x; c[v * 4 + 1] = q.y;
            c[v * 4 + 2] = q.z; c[v * 4 + 3] = q.w;
        }
#pragma unroll
        for (int k = 0; k < 20; k++) s += c[k];
    } else {
#pragma unroll
        for (int k = 0; k < 20; k++) c[k] = 0;
    }

    int inc = s;
#pragma unroll
    for (int off = 1; off < 32; off <<= 1) {
        int v = __shfl_up_sync(0xffffffffu, inc, off);
        if (lane >= off) inc += v;
    }
    if (lane == 31) warp_sum[wid] = inc;
    __syncthreads();

    if (wid == 0) {
        int ws = warp_sum[lane];
        int wi = ws;
#pragma unroll
        for (int off = 1; off < 32; off <<= 1) {
            int v = __shfl_up_sync(0xffffffffu, wi, off);
            if (lane >= off) wi += v;
        }
        warp_sum[lane] = wi - ws;                 // exclusive warp prefix
        if (lane == 31) s_total = wi;
    }
    __syncthreads();

    if (active) {
        int run = warp_sum[wid] + (inc - s);
#pragma unroll
        for (int k = 0; k < 20; k++) {
            g_start[base + k]  = run;
            g_cursor[base + k] = run;
            run += c[k];
        }
        int4* z4 = (int4*)(g_count + base);
#pragma unroll
        for (int v = 0; v < 5; v++) z4[v] = make_int4(0, 0, 0, 0);
    }
    if (t == 0) g_start[N_NODES] = s_total;
}

// ============================================================================
// K4: scatter + edge-parallel spherical harmonics.
//     One thread per edge: slot = cursor++, write row id + sh[16] at slot.
// ============================================================================
__global__ void k_scatter_sh(const int* __restrict__ ei,
                             const float* __restrict__ pos)
{
    const int e = blockIdx.x * blockDim.x + threadIdx.x;
    if (e >= N_EDGES) return;

    const int r = ei[e];                 // row (sender)
    const int c = ei[N_EDGES + e];       // col (destination)
    const int slot = atomicAdd(&g_cursor[c], 1);
    g_edge_row[slot] = r;

    float rx = pos[c * 3 + 0] - pos[r * 3 + 0];
    float ry = pos[c * 3 + 1] - pos[r * 3 + 1];
    float rz = pos[c * 3 + 2] - pos[r * 3 + 2];
    float inv = rsqrtf(fmaf(rx, rx, fmaf(ry, ry, fmaf(rz, rz, 1e-12f))));
    float X = rx * inv, Y = ry * inv, Z = rz * inv;
    float X2 = X * X, Y2 = Y * Y, Z2 = Z * Z;

    float4* q = (float4*)(g_sh + slot * SH_DIM);
    // sh[0] is the constant 0.28209479...; slot 0 stores sh1 shifted layout:
    // layout: [sh1..sh15, pad] so aggr uses 15 FMAs + constant fold for sh0.
    q[0] = make_float4(0.4886025119029199f * Y,
                       0.4886025119029199f * Z,
                       0.4886025119029199f * X,
                       1.0925484305920792f * X * Y);
    q[1] = make_float4(1.0925484305920792f * Y * Z,
                       0.31539156525252005f * (3.0f * Z2 - 1.0f),
                       1.0925484305920792f * X * Z,
                       0.5462742152960396f * (X2 - Y2));
    q[2] = make_float4(0.5900435899266435f * Y * (3.0f * X2 - Y2),
                       2.890611442640554f  * X * Y * Z,
                       0.4570457994644658f * Y * (5.0f * Z2 - 1.0f),
                       0.3731763325901154f * Z * (5.0f * Z2 - 3.0f));
    q[3] = make_float4(0.4570457994644658f * X * (5.0f * Z2 - 1.0f),
                       1.445305721320277f  * Z * (X2 - Y2),
                       0.5900435899266435f * X * (X2 - 3.0f * Y2),
                       0.0f);
}

// ============================================================================
// K5: gather-aggregate — one warp per destination node; lanes 0..19 own one
//     sender channel. Per edge: 1 uniform row load, 1 coalesced x gather,
//     4 uniform LDG.128 of sh, 16 FMA. 2x unrolled.
// ============================================================================
__global__ void k_aggr2(const float* __restrict__ x,
                        float* __restrict__ out)
{
    const int warp = (blockIdx.x * blockDim.x + threadIdx.x) >> 5;
    const int lane = threadIdx.x & 31;
    if (warp >= N_NODES) return;
    const int n = warp;

    const int s0 = g_start[n];
    const int s1 = g_start[n + 1];

    float accS = 0.0f;
    float acc[15];
#pragma unroll
    for (int j = 0; j < 15; j++) acc[j] = 0.0f;

    const float4* shp = (const float4*)g_sh;

    int slot = s0;
    for (; slot + 2 <= s1; slot += 2) {
        // batch all loads up front
        const int r0 = g_edge_row[slot];
        const int r1 = g_edge_row[slot + 1];
        const float sA = (lane < IN_DIM) ? __ldg(&x[r0 * IN_DIM + lane]) : 0.0f;
        const float sB = (lane < IN_DIM) ? __ldg(&x[r1 * IN_DIM + lane]) : 0.0f;
        const float4 a0 = __ldg(&shp[(slot    ) * 4 + 0]);
        const float4 a1 = __ldg(&shp[(slot    ) * 4 + 1]);
        const float4 a2 = __ldg(&shp[(slot    ) * 4 + 2]);
        const float4 a3 = __ldg(&shp[(slot    ) * 4 + 3]);
        const float4 b0 = __ldg(&shp[(slot + 1) * 4 + 0]);
        const float4 b1 = __ldg(&shp[(slot + 1) * 4 + 1]);
        const float4 b2 = __ldg(&shp[(slot + 1) * 4 + 2]);
        const float4 b3 = __ldg(&shp[(slot + 1) * 4 + 3]);

        accS += sA + sB;
        acc[0]  = fmaf(sA, a0.x, fmaf(sB, b0.x, acc[0]));
        acc[1]  = fmaf(sA, a0.y, fmaf(sB, b0.y, acc[1]));
        acc[2]  = fmaf(sA, a0.z, fmaf(sB, b0.z, acc[2]));
        acc[3]  = fmaf(sA, a0.w, fmaf(sB, b0.w, acc[3]));
        acc[4]  = fmaf(sA, a1.x, fmaf(sB, b1.x, acc[4]));
        acc[5]  = fmaf(sA, a1.y, fmaf(sB, b1.y, acc[5]));
        acc[6]  = fmaf(sA, a1.z, fmaf(sB, b1.z, acc[6]));
        acc[7]  = fmaf(sA, a1.w, fmaf(sB, b1.w, acc[7]));
        acc[8]  = fmaf(sA, a2.x, fmaf(sB, b2.x, acc[8]));
        acc[9]  = fmaf(sA, a2.y, fmaf(sB, b2.y, acc[9]));
        acc[10] = fmaf(sA, a2.z, fmaf(sB, b2.z, acc[10]));
        acc[11] = fmaf(sA, a2.w, fmaf(sB, b2.w, acc[11]));
        acc[12] = fmaf(sA, a3.x, fmaf(sB, b3.x, acc[12]));
        acc[13] = fmaf(sA, a3.y, fmaf(sB, b3.y, acc[13]));
        acc[14] = fmaf(sA, a3.z, fmaf(sB, b3.z, acc[14]));
    }
    if (slot < s1) {
        const int r0 = g_edge_row[slot];
        const float sA = (lane < IN_DIM) ? __ldg(&x[r0 * IN_DIM + lane]) : 0.0f;
        const float4 a0 = __ldg(&shp[slot * 4 + 0]);
        const float4 a1 = __ldg(&shp[slot * 4 + 1]);
        const float4 a2 = __ldg(&shp[slot * 4 + 2]);
        const float4 a3 = __ldg(&shp[slot * 4 + 3]);
        accS += sA;
        acc[0]  = fmaf(sA, a0.x, acc[0]);
        acc[1]  = fmaf(sA, a0.y, acc[1]);
        acc[2]  = fmaf(sA, a0.z, acc[2]);
        acc[3]  = fmaf(sA, a0.w, acc[3]);
        acc[4]  = fmaf(sA, a1.x, acc[4]);
        acc[5]  = fmaf(sA, a1.y, acc[5]);
        acc[6]  = fmaf(sA, a1.z, acc[6]);
        acc[7]  = fmaf(sA, a1.w, acc[7]);
        acc[8]  = fmaf(sA, a2.x, acc[8]);
        acc[9]  = fmaf(sA, a2.y, acc[9]);
        acc[10] = fmaf(sA, a2.z, acc[10]);
        acc[11] = fmaf(sA, a2.w, acc[11]);
        acc[12] = fmaf(sA, a3.x, acc[12]);
        acc[13] = fmaf(sA, a3.y, acc[13]);
        acc[14] = fmaf(sA, a3.z, acc[14]);
    }

    if (lane < IN_DIM) {
        float* base = out + n * OUT_DIM;
        base[20 + lane] = accS;
        float4* p = (float4*)(base + 40 + lane * SH_DIM);
        p[0] = make_float4(accS * 0.28209479177387814f, acc[0],  acc[1],  acc[2]);
        p[1] = make_float4(acc[3],  acc[4],  acc[5],  acc[6]);
        p[2] = make_float4(acc[7],  acc[8],  acc[9],  acc[10]);
        p[3] = make_float4(acc[11], acc[12], acc[13], acc[14]);
    }
}

// ============================================================================
extern "C" void kernel_launch(void* const* d_in, const int* in_sizes, int n_in,
                              void* d_out, int out_size)
{
    const float* x     = (const float*)d_in[0];
    const float* pos   = (const float*)d_in[1];
    const int*   ei    = (const int*)  d_in[2];
    const float* Wpre  = (const float*)d_in[3];
    const float* bpre  = (const float*)d_in[4];
    const float* Wpost = (const float*)d_in[5];
    const float* bpost = (const float*)d_in[6];
    const float* Wsc   = (const float*)d_in[7];
    const float* bsc   = (const float*)d_in[8];
    float* out = (float*)d_out;

    k_mlp <<<(N_NODES + 255) / 256, 256>>>(x, Wpre, bpre, Wpost, bpost, Wsc, bsc, out);
    k_hist<<<(N_EDGES + 255) / 256, 256>>>(ei);
    k_scan<<<1, 1024>>>();
    k_scatter_sh<<<(N_EDGES + 255) / 256, 256>>>(ei, pos);
    k_aggr2<<<(N_NODES * 32 + 255) / 256, 256>>>(x, out);
}